// round 6
// baseline (speedup 1.0000x reference)
#include <cuda_runtime.h>
#include <cstdint>

#define N_NODES   100000
#define N_EDGES   1600000
#define D         32
#define OUT_FEAT  32

// Device-global scratch. g_agg is zero-initialized at module load and
// re-zeroed by final_kernel at the end of every call (after consumption),
// so every kernel_launch sees a zeroed accumulator — no memset node needed.
__device__ __align__(16) float g_agg[N_NODES * D];
__device__ __align__(16) float g_partial[N_NODES * D];   // node@W1[0:32] + gb

#define TPB  128

#define S_LANES      (N_EDGES * 8)            // 12.8M float4 lanes
#define S_PER_BLOCK  1024                     // 128 threads x 8 lanes
#define S_BLOCKS     (S_LANES / S_PER_BLOCK)  // 12500 exactly

#define NBP  128                              // nodes/block, partial path
#define P_BLOCKS     ((N_NODES + NBP - 1) / NBP)   // 782
#define XSTRP 33
#define SMEM1_FLOATS (NBP * XSTRP + 32 * 32 + 32)

#define NBF  64                               // nodes/block, final kernel
#define F_BLOCKS     ((N_NODES + NBF - 1) / NBF)   // 1563
#define XSTR 33
#define SMEM2_FLOATS (NBF * XSTR + 32 * 32 + 32 * 32 + 32)

// ---------------------------------------------------------------------------
// Kernel A (fused grid, scatter FIRST): blocks [0, S_BLOCKS) do the edge
// scatter-add (LTS-bound red.v4, saturates from wave 1); blocks
// [S_BLOCKS, S_BLOCKS+P_BLOCKS) compute the scatter-independent partial term
// P = node_attr @ W1[0:32] + (b1 + global @ W1[64:96]) in the ragged tail.
// ---------------------------------------------------------------------------
__global__ __launch_bounds__(TPB) void fused_scatter_partial(
    const float* __restrict__ edge_attr,
    const int* __restrict__ receivers,
    const float* __restrict__ node_attr,
    const float* __restrict__ global_attr,
    const float* __restrict__ W1,
    const float* __restrict__ b1)
{
    const int tid = threadIdx.x;

    if (blockIdx.x < S_BLOCKS) {
        // ---------------- scatter path: 8 independent lanes/thread ----------
        const int lane0 = blockIdx.x * S_PER_BLOCK + tid;
        float4 v[8];
        int    r[8];
        #pragma unroll
        for (int t = 0; t < 8; t++) {
            int lane = lane0 + 128 * t;
            r[t] = receivers[lane >> 3];
            v[t] = reinterpret_cast<const float4*>(edge_attr)[lane];
        }
        #pragma unroll
        for (int t = 0; t < 8; t++) {
            int lane = lane0 + 128 * t;
            int c = lane & 7;
            if ((unsigned)r[t] < N_NODES) {
                float* dst = g_agg + (size_t)r[t] * D + c * 4;
                asm volatile("red.global.add.v4.f32 [%0], {%1, %2, %3, %4};"
                             :: "l"(dst), "f"(v[t].x), "f"(v[t].y),
                                "f"(v[t].z), "f"(v[t].w)
                             : "memory");
            }
        }
        return;
    }

    // ---------------- partial-MLP path (4 nodes x 8 cols per thread) -------
    extern __shared__ float smem[];
    float* xs  = smem;                  // [NBP][XSTRP]
    float* w1s = xs + NBP * XSTRP;      // [32][32]  W1 rows 0..31
    float* gb  = w1s + 32 * 32;         // [32]

    const int cg   = tid & 3;
    const int q    = tid >> 2;
    const int base = (blockIdx.x - S_BLOCKS) * NBP;
    const int nvalid = min(NBP, N_NODES - base);
    const bool full  = (nvalid == NBP);

    {
        const float4* w1v = reinterpret_cast<const float4*>(W1);
        float4 a0 = w1v[tid], a1 = w1v[tid + 128];
        reinterpret_cast<float4*>(w1s)[tid]       = a0;
        reinterpret_cast<float4*>(w1s)[tid + 128] = a1;
    }
    if (tid < 32) {
        float acc = b1[tid];
        #pragma unroll
        for (int k = 0; k < D; k++)
            acc = fmaf(global_attr[k], W1[(64 + k) * 32 + tid], acc);
        gb[tid] = acc;
    }
    {
        const float4* nav = reinterpret_cast<const float4*>(node_attr) + (size_t)base * 8;
        float4 va[8];
        #pragma unroll
        for (int t = 0; t < 8; t++) {
            int idx = tid + 128 * t;
            if (full || (idx >> 3) < nvalid) va[t] = nav[idx];
            else va[t] = make_float4(0, 0, 0, 0);
        }
        #pragma unroll
        for (int t = 0; t < 8; t++) {
            int idx = tid + 128 * t;
            int n = idx >> 3, c = idx & 7;
            float* p = &xs[n * XSTRP + 4 * c];
            p[0] = va[t].x; p[1] = va[t].y; p[2] = va[t].z; p[3] = va[t].w;
        }
    }
    __syncthreads();

    float acc[4][8];
    #pragma unroll
    for (int j = 0; j < 4; j++)
        #pragma unroll
        for (int m = 0; m < 8; m++) acc[j][m] = gb[cg * 8 + m];

    const float* x0 = &xs[(4 * q + 0) * XSTRP];
    const float* x1 = &xs[(4 * q + 1) * XSTRP];
    const float* x2 = &xs[(4 * q + 2) * XSTRP];
    const float* x3 = &xs[(4 * q + 3) * XSTRP];

    #pragma unroll 4
    for (int k = 0; k < 32; k++) {
        float4 wa = *reinterpret_cast<const float4*>(&w1s[k * 32 + cg * 8]);
        float4 wb = *reinterpret_cast<const float4*>(&w1s[k * 32 + cg * 8 + 4]);
        float w[8] = {wa.x, wa.y, wa.z, wa.w, wb.x, wb.y, wb.z, wb.w};
        float xv[4] = {x0[k], x1[k], x2[k], x3[k]};
        #pragma unroll
        for (int j = 0; j < 4; j++)
            #pragma unroll
            for (int m = 0; m < 8; m++)
                acc[j][m] = fmaf(xv[j], w[m], acc[j][m]);
    }

    #pragma unroll
    for (int j = 0; j < 4; j++) {
        int n = 4 * q + j;
        if (n < nvalid) {
            float* dst = g_partial + (size_t)(base + n) * D + cg * 8;
            reinterpret_cast<float4*>(dst)[0] =
                make_float4(acc[j][0], acc[j][1], acc[j][2], acc[j][3]);
            reinterpret_cast<float4*>(dst)[1] =
                make_float4(acc[j][4], acc[j][5], acc[j][6], acc[j][7]);
        }
    }
}

// ---------------------------------------------------------------------------
// Kernel B: out = relu(P + agg @ W1[32:64]) @ W2 + b2, NB=64 nodes/block
// (1563 blocks -> ~10.5 blocks/SM, occ ~65%). Each thread: 2 nodes x 8 cols.
// Also re-zeroes its g_agg range after staging (replaces the memset node).
// ---------------------------------------------------------------------------
__global__ __launch_bounds__(TPB) void final_kernel(
    const float* __restrict__ W1,
    const float* __restrict__ W2, const float* __restrict__ b2,
    float* __restrict__ out)
{
    extern __shared__ float smem[];
    float* xs  = smem;                 // [NBF][XSTR] agg; reused as ht
    float* w1s = xs + NBF * XSTR;      // [32][32]  W1 rows 32..63
    float* w2s = w1s + 32 * 32;        // [32][32]
    float* b2s = w2s + 32 * 32;        // [32]

    const int tid  = threadIdx.x;
    const int cg   = tid & 3;
    const int q    = tid >> 2;         // node pair: 2q, 2q+1
    const int base = blockIdx.x * NBF;
    const int nvalid = min(NBF, N_NODES - base);
    const bool full  = (nvalid == NBF);

    // stage W1 rows 32..63 (f4 offset 256) and W2: 2+2 LDG.128/thread
    {
        const float4* w1v = reinterpret_cast<const float4*>(W1);
        const float4* w2v = reinterpret_cast<const float4*>(W2);
        float4 a0 = w1v[256 + tid], a1 = w1v[256 + tid + 128];
        float4 c0 = w2v[tid],       c1 = w2v[tid + 128];
        reinterpret_cast<float4*>(w1s)[tid]       = a0;
        reinterpret_cast<float4*>(w1s)[tid + 128] = a1;
        reinterpret_cast<float4*>(w2s)[tid]       = c0;
        reinterpret_cast<float4*>(w2s)[tid + 128] = c1;
    }
    if (tid < 32) b2s[tid] = b2[tid];

    // stage agg rows (L2-hot): 512 f4 -> 4/thread; then re-zero them
    {
        float4* agv = reinterpret_cast<float4*>(g_agg) + (size_t)base * 8;
        float4 vb[4];
        #pragma unroll
        for (int t = 0; t < 4; t++) {
            int idx = tid + 128 * t;
            if (full || (idx >> 3) < nvalid) vb[t] = agv[idx];
            else vb[t] = make_float4(0, 0, 0, 0);
        }
        #pragma unroll
        for (int t = 0; t < 4; t++) {
            int idx = tid + 128 * t;
            int n = idx >> 3, c = idx & 7;
            float* p = &xs[n * XSTR + 4 * c];
            p[0] = vb[t].x; p[1] = vb[t].y; p[2] = vb[t].z; p[3] = vb[t].w;
        }
        // re-zero for the next call (same thread read it above, no race)
        const float4 z = make_float4(0, 0, 0, 0);
        #pragma unroll
        for (int t = 0; t < 4; t++) {
            int idx = tid + 128 * t;
            if (full || (idx >> 3) < nvalid) agv[idx] = z;
        }
    }

    // load this thread's P tile (2 nodes x 8 cols), coalesced-ish from L2
    float acc[2][8];
    {
        const float4* pv = reinterpret_cast<const float4*>(g_partial) + (size_t)base * 8;
        #pragma unroll
        for (int j = 0; j < 2; j++) {
            int n = 2 * q + j;
            float4 pa, pb;
            if (full || n < nvalid) {
                pa = pv[n * 8 + cg * 2];
                pb = pv[n * 8 + cg * 2 + 1];
            } else { pa = make_float4(0,0,0,0); pb = pa; }
            acc[j][0] = pa.x; acc[j][1] = pa.y; acc[j][2] = pa.z; acc[j][3] = pa.w;
            acc[j][4] = pb.x; acc[j][5] = pb.y; acc[j][6] = pb.z; acc[j][7] = pb.w;
        }
    }
    __syncthreads();

    // layer 1 remainder: += agg @ W1[32:64]
    const float* x0 = &xs[(2 * q + 0) * XSTR];
    const float* x1 = &xs[(2 * q + 1) * XSTR];

    #pragma unroll 4
    for (int k = 0; k < 32; k++) {
        float4 wa = *reinterpret_cast<const float4*>(&w1s[k * 32 + cg * 8]);
        float4 wb = *reinterpret_cast<const float4*>(&w1s[k * 32 + cg * 8 + 4]);
        float w[8] = {wa.x, wa.y, wa.z, wa.w, wb.x, wb.y, wb.z, wb.w};
        float xv[2] = {x0[k], x1[k]};
        #pragma unroll
        for (int j = 0; j < 2; j++)
            #pragma unroll
            for (int m = 0; m < 8; m++)
                acc[j][m] = fmaf(xv[j], w[m], acc[j][m]);
    }

    // relu + round-trip h through smem (reuse xs region)
    __syncthreads();
    float* ht = xs;   // [NBF][XSTR]
    #pragma unroll
    for (int j = 0; j < 2; j++) {
        int n = 2 * q + j;
        #pragma unroll
        for (int m = 0; m < 8; m++)
            ht[n * XSTR + cg * 8 + m] = fmaxf(acc[j][m], 0.f);
    }
    __syncthreads();

    // layer 2
    float o[2][8];
    #pragma unroll
    for (int j = 0; j < 2; j++)
        #pragma unroll
        for (int m = 0; m < 8; m++) o[j][m] = b2s[cg * 8 + m];

    const float* h0 = &ht[(2 * q + 0) * XSTR];
    const float* h1 = &ht[(2 * q + 1) * XSTR];

    #pragma unroll 4
    for (int i = 0; i < 32; i++) {
        float4 wa = *reinterpret_cast<const float4*>(&w2s[i * 32 + cg * 8]);
        float4 wb = *reinterpret_cast<const float4*>(&w2s[i * 32 + cg * 8 + 4]);
        float w[8] = {wa.x, wa.y, wa.z, wa.w, wb.x, wb.y, wb.z, wb.w};
        float hv[2] = {h0[i], h1[i]};
        #pragma unroll
        for (int j = 0; j < 2; j++)
            #pragma unroll
            for (int m = 0; m < 8; m++)
                o[j][m] = fmaf(hv[j], w[m], o[j][m]);
    }

    #pragma unroll
    for (int j = 0; j < 2; j++) {
        int n = 2 * q + j;
        if (n < nvalid) {
            float* dst = out + (size_t)(base + n) * OUT_FEAT + cg * 8;
            reinterpret_cast<float4*>(dst)[0] =
                make_float4(o[j][0], o[j][1], o[j][2], o[j][3]);
            reinterpret_cast<float4*>(dst)[1] =
                make_float4(o[j][4], o[j][5], o[j][6], o[j][7]);
        }
    }
}

// ---------------------------------------------------------------------------
// Launch.
// ---------------------------------------------------------------------------
extern "C" void kernel_launch(void* const* d_in, const int* in_sizes, int n_in,
                              void* d_out, int out_size) {
    const float* node_attr   = (const float*)d_in[0];
    const int*   edge_index  = (const int*)d_in[1];
    const float* edge_attr   = (const float*)d_in[2];
    const float* global_attr = (const float*)d_in[3];
    const float* W1          = (const float*)d_in[4];
    const float* b1          = (const float*)d_in[5];
    const float* W2          = (const float*)d_in[6];
    const float* b2          = (const float*)d_in[7];
    float*       out         = (float*)d_out;

    const int* receivers = edge_index + N_EDGES;

    // 1) fused scatter (first) + partial MLP (tail). g_agg is already zero:
    //    zero-initialized at load, re-zeroed by final_kernel every call.
    {
        size_t smem1 = SMEM1_FLOATS * sizeof(float);
        cudaFuncSetAttribute(fused_scatter_partial,
                             cudaFuncAttributeMaxDynamicSharedMemorySize,
                             (int)smem1);
        fused_scatter_partial<<<S_BLOCKS + P_BLOCKS, TPB, smem1>>>(
            edge_attr, receivers, node_attr, global_attr, W1, b1);
    }

    // 2) final: relu(P + agg@W1b) @ W2 + b2; also re-zeroes g_agg
    {
        size_t smem2 = SMEM2_FLOATS * sizeof(float);
        cudaFuncSetAttribute(final_kernel,
                             cudaFuncAttributeMaxDynamicSharedMemorySize,
                             (int)smem2);
        final_kernel<<<F_BLOCKS, TPB, smem2>>>(W1, W2, b2, out);
    }
    (void)in_sizes; (void)n_in; (void)out_size;
}